// round 3
// baseline (speedup 1.0000x reference)
#include <cuda_runtime.h>
#include <math.h>

#define BATCH 8
#define SEQ   1213
#define HID   768
#define NH    12
#define DH    64
#define INTER 3072
#define MROWS (BATCH*SEQ)   // 9704
#define NUM_LEAD 12
#define PATCHES 100

// ---------------- scratch (device globals; no allocation allowed) ----------------
__device__ float g_q   [(size_t)MROWS*HID];
__device__ float g_k   [(size_t)MROWS*HID];
__device__ float g_v   [(size_t)MROWS*HID];
__device__ float g_ctx [(size_t)MROWS*HID];
__device__ float g_t1  [(size_t)MROWS*HID];
__device__ float g_attn[(size_t)MROWS*HID];
__device__ float g_int [(size_t)MROWS*INTER];

// ---------------- SGEMM core (128x128x8 double-buffered) ------------------------
// epi: 0 = bias, 1 = bias+residual, 2 = bias+gelu(exact erf)
__device__ __forceinline__ float gelu_exact(float x) {
    return 0.5f * x * (1.0f + erff(x * 0.7071067811865476f));
}

__device__ __forceinline__
void sgemm_body(const float* __restrict__ A, const float* __restrict__ B,
                const float* __restrict__ bias, const float* __restrict__ res,
                float* __restrict__ C, int M, int N, int K, int epi,
                int bx, int by)
{
    const int BM = 128, BN = 128, BK = 8;
    __shared__ float As[2][BK][BM];
    __shared__ float Bs[2][BK][BN];

    int tid  = threadIdx.x;
    int row0 = by * BM;
    int col0 = bx * BN;
    int tr = tid >> 4;          // 0..15
    int tc = tid & 15;          // 0..15

    int arow = tid >> 1;        // 0..127
    int acol = (tid & 1) * 4;   // 0 or 4
    int brow = tid >> 5;        // 0..7
    int bcol = (tid & 31) * 4;  // 0..124

    const float* Aptr = A + (size_t)(row0 + arow) * K + acol;
    const float* Bptr = B + (size_t)brow * N + col0 + bcol;
    bool aval = (row0 + arow) < M;

    float acc[8][8];
    #pragma unroll
    for (int i = 0; i < 8; i++)
        #pragma unroll
        for (int j = 0; j < 8; j++) acc[i][j] = 0.0f;

    float4 a4 = aval ? *(const float4*)Aptr : make_float4(0,0,0,0);
    float4 b4 = *(const float4*)Bptr;
    As[0][acol+0][arow] = a4.x;
    As[0][acol+1][arow] = a4.y;
    As[0][acol+2][arow] = a4.z;
    As[0][acol+3][arow] = a4.w;
    *(float4*)&Bs[0][brow][bcol] = b4;
    __syncthreads();

    int nt = K / BK;
    for (int t = 0; t < nt; t++) {
        int cur = t & 1;
        if (t + 1 < nt) {
            a4 = aval ? *(const float4*)(Aptr + (size_t)(t+1)*BK) : make_float4(0,0,0,0);
            b4 = *(const float4*)(Bptr + (size_t)(t+1)*BK*N);
        }
        #pragma unroll
        for (int kk = 0; kk < BK; kk++) {
            float4 av0 = *(const float4*)&As[cur][kk][tr*8];
            float4 av1 = *(const float4*)&As[cur][kk][tr*8+4];
            float4 bv0 = *(const float4*)&Bs[cur][kk][tc*8];
            float4 bv1 = *(const float4*)&Bs[cur][kk][tc*8+4];
            float rA[8] = {av0.x,av0.y,av0.z,av0.w,av1.x,av1.y,av1.z,av1.w};
            float rB[8] = {bv0.x,bv0.y,bv0.z,bv0.w,bv1.x,bv1.y,bv1.z,bv1.w};
            #pragma unroll
            for (int i = 0; i < 8; i++)
                #pragma unroll
                for (int j = 0; j < 8; j++)
                    acc[i][j] += rA[i] * rB[j];
        }
        if (t + 1 < nt) {
            int nx = cur ^ 1;
            As[nx][acol+0][arow] = a4.x;
            As[nx][acol+1][arow] = a4.y;
            As[nx][acol+2][arow] = a4.z;
            As[nx][acol+3][arow] = a4.w;
            *(float4*)&Bs[nx][brow][bcol] = b4;
        }
        __syncthreads();
    }

    #pragma unroll
    for (int i = 0; i < 8; i++) {
        int r = row0 + tr*8 + i;
        if (r >= M) continue;
        #pragma unroll
        for (int j4 = 0; j4 < 8; j4 += 4) {
            int c = col0 + tc*8 + j4;
            float4 bv = *(const float4*)&bias[c];
            float4 o;
            o.x = acc[i][j4+0] + bv.x;
            o.y = acc[i][j4+1] + bv.y;
            o.z = acc[i][j4+2] + bv.z;
            o.w = acc[i][j4+3] + bv.w;
            if (epi == 1) {
                float4 rv = *(const float4*)&res[(size_t)r*N + c];
                o.x += rv.x; o.y += rv.y; o.z += rv.z; o.w += rv.w;
            } else if (epi == 2) {
                o.x = gelu_exact(o.x); o.y = gelu_exact(o.y);
                o.z = gelu_exact(o.z); o.w = gelu_exact(o.w);
            }
            *(float4*)&C[(size_t)r*N + c] = o;
        }
    }
}

__global__ __launch_bounds__(256)
void sgemm_kernel(const float* __restrict__ A, const float* __restrict__ B,
                  const float* __restrict__ bias, const float* __restrict__ res,
                  float* __restrict__ C, int M, int N, int K, int epi)
{
    sgemm_body(A, B, bias, res, C, M, N, K, epi, blockIdx.x, blockIdx.y);
}

// Fused QKV: grid.z = 0/1/2 selects (Wq,bq,q) / (Wk,bk,k) / (Wv,bv,v)
__global__ __launch_bounds__(256)
void qkv_kernel(const float* __restrict__ X,
                const float* __restrict__ Wq, const float* __restrict__ bq,
                const float* __restrict__ Wk, const float* __restrict__ bk,
                const float* __restrict__ Wv, const float* __restrict__ bv,
                float* __restrict__ q, float* __restrict__ k, float* __restrict__ v)
{
    const float* W; const float* bb; float* out;
    if (blockIdx.z == 0)      { W = Wq; bb = bq; out = q; }
    else if (blockIdx.z == 1) { W = Wk; bb = bk; out = k; }
    else                      { W = Wv; bb = bv; out = v; }
    sgemm_body(X, W, bb, nullptr, out, MROWS, HID, HID, 0, blockIdx.x, blockIdx.y);
}

// ---------------- Flash attention (fp32), 64x64 tiles ---------------------------
__device__ __forceinline__ float lead_bias(int r, int c) {
    if (r == 0) return (c >= 1 && c < NUM_LEAD + 1) ? -99999.0f : 0.0f;
    if (r <= NUM_LEAD) {
        int st = NUM_LEAD + 1 + PATCHES * (r - 1);
        return (c >= st && c < st + PATCHES) ? 0.0f : -99999.0f;
    }
    return 0.0f;
}

__global__ __launch_bounds__(256)
void flash_kernel(const float* __restrict__ q, const float* __restrict__ k,
                  const float* __restrict__ v, const float* __restrict__ amask,
                  float* __restrict__ ctx)
{
    __shared__ float Qt [64*64];
    __shared__ float KPs[64*64];
    __shared__ float Vs [64*64];

    int tid = threadIdx.x;
    int qt  = blockIdx.x;
    int h   = blockIdx.y;
    int b   = blockIdx.z;
    int q0  = qt * 64;
    int ty  = tid >> 4;   // 0..15
    int tx  = tid & 15;   // 0..15

    // load Q tile transposed: Qt[d][r]
    {
        int r  = tid >> 2;
        int c0 = (tid & 3) * 16;
        int gr = q0 + r;
        const float* src = q + (size_t)(b*SEQ + (gr < SEQ ? gr : SEQ-1))*HID + h*DH + c0;
        #pragma unroll
        for (int i = 0; i < 16; i += 4) {
            float4 val = (gr < SEQ) ? *(const float4*)(src + i) : make_float4(0,0,0,0);
            Qt[(c0+i+0)*64 + r] = val.x;
            Qt[(c0+i+1)*64 + r] = val.y;
            Qt[(c0+i+2)*64 + r] = val.z;
            Qt[(c0+i+3)*64 + r] = val.w;
        }
    }

    float o[4][4];
    #pragma unroll
    for (int i = 0; i < 4; i++)
        #pragma unroll
        for (int j = 0; j < 4; j++) o[i][j] = 0.0f;
    float m[4] = {-1e30f,-1e30f,-1e30f,-1e30f};
    float l[4] = {0,0,0,0};

    int ntile = (SEQ + 63) / 64;
    for (int t = 0; t < ntile; t++) {
        int k0 = t * 64;
        __syncthreads();

        {
            int r  = tid >> 2;
            int c0 = (tid & 3) * 16;
            int gsr = k0 + r;
            bool ok = gsr < SEQ;
            const float* ks = k + (size_t)(b*SEQ + (ok ? gsr : SEQ-1))*HID + h*DH + c0;
            const float* vs = v + (size_t)(b*SEQ + (ok ? gsr : SEQ-1))*HID + h*DH + c0;
            #pragma unroll
            for (int i = 0; i < 16; i += 4) {
                float4 kv = ok ? *(const float4*)(ks + i) : make_float4(0,0,0,0);
                float4 vv = ok ? *(const float4*)(vs + i) : make_float4(0,0,0,0);
                KPs[(c0+i+0)*64 + r] = kv.x;
                KPs[(c0+i+1)*64 + r] = kv.y;
                KPs[(c0+i+2)*64 + r] = kv.z;
                KPs[(c0+i+3)*64 + r] = kv.w;
                *(float4*)&Vs[r*64 + c0+i] = vv;
            }
        }
        __syncthreads();

        float acc[4][4];
        #pragma unroll
        for (int i = 0; i < 4; i++)
            #pragma unroll
            for (int j = 0; j < 4; j++) acc[i][j] = 0.0f;
        #pragma unroll 16
        for (int kk = 0; kk < 64; kk++) {
            float4 qv = *(const float4*)&Qt [kk*64 + ty*4];
            float4 kv = *(const float4*)&KPs[kk*64 + tx*4];
            float qa[4] = {qv.x,qv.y,qv.z,qv.w};
            float ka[4] = {kv.x,kv.y,kv.z,kv.w};
            #pragma unroll
            for (int i = 0; i < 4; i++)
                #pragma unroll
                for (int j = 0; j < 4; j++)
                    acc[i][j] += qa[i] * ka[j];
        }

        int gcb = k0 + tx*4;
        float amv[4];
        #pragma unroll
        for (int j = 0; j < 4; j++)
            amv[j] = (gcb + j < SEQ) ? amask[(size_t)b*SEQ + gcb + j] : 0.0f;
        #pragma unroll
        for (int i = 0; i < 4; i++) {
            int gr = q0 + ty*4 + i;
            #pragma unroll
            for (int j = 0; j < 4; j++) {
                int gc = gcb + j;
                float sc = acc[i][j] * 0.125f + amv[j];
                if (q0 == 0) sc += lead_bias(gr, gc);
                if (gc >= SEQ) sc = -1e30f;
                acc[i][j] = sc;
            }
        }

        #pragma unroll
        for (int i = 0; i < 4; i++) {
            float mt = fmaxf(fmaxf(acc[i][0], acc[i][1]), fmaxf(acc[i][2], acc[i][3]));
            #pragma unroll
            for (int off = 8; off >= 1; off >>= 1)
                mt = fmaxf(mt, __shfl_xor_sync(0xffffffffu, mt, off));
            float mn = fmaxf(m[i], mt);
            float corr = __expf(m[i] - mn);
            m[i] = mn;
            float rs = 0.0f;
            #pragma unroll
            for (int j = 0; j < 4; j++) {
                acc[i][j] = __expf(acc[i][j] - mn);
                rs += acc[i][j];
            }
            #pragma unroll
            for (int off = 8; off >= 1; off >>= 1)
                rs += __shfl_xor_sync(0xffffffffu, rs, off);
            l[i] = l[i] * corr + rs;
            #pragma unroll
            for (int j = 0; j < 4; j++) o[i][j] *= corr;
        }

        __syncthreads();

        #pragma unroll
        for (int i = 0; i < 4; i++) {
            float4 p4 = make_float4(acc[i][0], acc[i][1], acc[i][2], acc[i][3]);
            *(float4*)&KPs[(ty*4 + i)*64 + tx*4] = p4;
        }
        __syncthreads();

        #pragma unroll 4
        for (int kk = 0; kk < 64; kk += 4) {
            float4 pv[4];
            #pragma unroll
            for (int i = 0; i < 4; i++)
                pv[i] = *(const float4*)&KPs[(ty*4 + i)*64 + kk];
            #pragma unroll
            for (int s = 0; s < 4; s++) {
                float4 vv = *(const float4*)&Vs[(kk + s)*64 + tx*4];
                float pvs[4] = { (&pv[0].x)[s], (&pv[1].x)[s], (&pv[2].x)[s], (&pv[3].x)[s] };
                #pragma unroll
                for (int i = 0; i < 4; i++) {
                    o[i][0] += pvs[i] * vv.x;
                    o[i][1] += pvs[i] * vv.y;
                    o[i][2] += pvs[i] * vv.z;
                    o[i][3] += pvs[i] * vv.w;
                }
            }
        }
    }

    #pragma unroll
    for (int i = 0; i < 4; i++) {
        int gr = q0 + ty*4 + i;
        if (gr >= SEQ) continue;
        float inv = 1.0f / l[i];
        float4 o4 = make_float4(o[i][0]*inv, o[i][1]*inv, o[i][2]*inv, o[i][3]*inv);
        *(float4*)&ctx[(size_t)(b*SEQ + gr)*HID + h*DH + tx*4] = o4;
    }
}

// ---------------- LayerNorm (two-pass, eps 1e-12) -------------------------------
__global__ __launch_bounds__(256)
void ln_kernel(const float* __restrict__ x, const float* __restrict__ g,
               const float* __restrict__ bta, float* __restrict__ y)
{
    __shared__ float red[8];
    int row = blockIdx.x;
    int tid = threadIdx.x;
    const float* xr = x + (size_t)row * HID;

    float v[3];
    float s = 0.0f;
    #pragma unroll
    for (int i = 0; i < 3; i++) { v[i] = xr[tid + i*256]; s += v[i]; }

    #pragma unroll
    for (int off = 16; off >= 1; off >>= 1) s += __shfl_xor_sync(0xffffffffu, s, off);
    if ((tid & 31) == 0) red[tid >> 5] = s;
    __syncthreads();
    s = red[0]+red[1]+red[2]+red[3]+red[4]+red[5]+red[6]+red[7];
    float mean = s * (1.0f / HID);
    __syncthreads();

    float s2 = 0.0f;
    #pragma unroll
    for (int i = 0; i < 3; i++) { float d = v[i] - mean; s2 += d * d; }
    #pragma unroll
    for (int off = 16; off >= 1; off >>= 1) s2 += __shfl_xor_sync(0xffffffffu, s2, off);
    if ((tid & 31) == 0) red[tid >> 5] = s2;
    __syncthreads();
    s2 = red[0]+red[1]+red[2]+red[3]+red[4]+red[5]+red[6]+red[7];
    float rstd = rsqrtf(s2 * (1.0f / HID) + 1e-12f);

    #pragma unroll
    for (int i = 0; i < 3; i++) {
        int c = tid + i*256;
        y[(size_t)row*HID + c] = g[c] * (v[i] - mean) * rstd + bta[c];
    }
}

// ---------------- launch --------------------------------------------------------
extern "C" void kernel_launch(void* const* d_in, const int* in_sizes, int n_in,
                              void* d_out, int out_size)
{
    const float* X     = (const float*)d_in[0];
    const float* amask = (const float*)d_in[1];
    const float* Wq = (const float*)d_in[2];  const float* bq = (const float*)d_in[3];
    const float* Wk = (const float*)d_in[4];  const float* bk = (const float*)d_in[5];
    const float* Wv = (const float*)d_in[6];  const float* bv = (const float*)d_in[7];
    const float* Wo = (const float*)d_in[8];  const float* bo = (const float*)d_in[9];
    const float* g1 = (const float*)d_in[10]; const float* b1 = (const float*)d_in[11];
    const float* Wi = (const float*)d_in[12]; const float* bi = (const float*)d_in[13];
    const float* Wd = (const float*)d_in[14]; const float* bd = (const float*)d_in[15];
    const float* g2 = (const float*)d_in[16]; const float* b2 = (const float*)d_in[17];

    float *q, *k, *v, *ctx, *t1, *attn, *inter;
    cudaGetSymbolAddress((void**)&q,     g_q);
    cudaGetSymbolAddress((void**)&k,     g_k);
    cudaGetSymbolAddress((void**)&v,     g_v);
    cudaGetSymbolAddress((void**)&ctx,   g_ctx);
    cudaGetSymbolAddress((void**)&t1,    g_t1);
    cudaGetSymbolAddress((void**)&attn,  g_attn);
    cudaGetSymbolAddress((void**)&inter, g_int);

    dim3 blk(256);
    dim3 gQKV(HID/128, (MROWS + 127)/128, 3);
    dim3 gH(HID/128, (MROWS + 127)/128);
    dim3 gI(INTER/128, (MROWS + 127)/128);

    qkv_kernel<<<gQKV, blk>>>(X, Wq, bq, Wk, bk, Wv, bv, q, k, v);

    dim3 gF((SEQ + 63)/64, NH, BATCH);
    flash_kernel<<<gF, blk>>>(q, k, v, amask, ctx);

    sgemm_kernel<<<gH, blk>>>(ctx, Wo, bo, X, t1, MROWS, HID, HID, 1);
    ln_kernel<<<MROWS, blk>>>(t1, g1, b1, attn);

    sgemm_kernel<<<gI, blk>>>(attn, Wi, bi, nullptr, inter, MROWS, INTER, HID, 2);
    sgemm_kernel<<<gH, blk>>>(inter, Wd, bd, attn, t1, MROWS, HID, INTER, 1);
    ln_kernel<<<MROWS, blk>>>(t1, g2, b2, (float*)d_out);
}

// round 4
// speedup vs baseline: 2.0075x; 2.0075x over previous
#include <cuda_runtime.h>
#include <cuda_bf16.h>
#include <math.h>
#include <stdint.h>

#define BATCH 8
#define SEQ   1213
#define HID   768
#define NH    12
#define DH    64
#define INTER 3072
#define MROWS (BATCH*SEQ)   // 9704
#define NUM_LEAD 12
#define PATCHES 100

// ---------------- scratch (device globals; no allocation allowed) ----------------
__device__ float g_q   [(size_t)MROWS*HID];
__device__ float g_k   [(size_t)MROWS*HID];
__device__ float g_v   [(size_t)MROWS*HID];
__device__ float g_ctx [(size_t)MROWS*HID];
__device__ float g_t1  [(size_t)MROWS*HID];
__device__ float g_attn[(size_t)MROWS*HID];
__device__ float g_int [(size_t)MROWS*INTER];

// bf16 split activation buffers (sized for largest A = inter)
__device__ __nv_bfloat16 g_ah[(size_t)MROWS*INTER];
__device__ __nv_bfloat16 g_al[(size_t)MROWS*INTER];
// transposed split weights [N][K]
__device__ __nv_bfloat16 g_wqh[HID*HID],  g_wql[HID*HID];
__device__ __nv_bfloat16 g_wkh[HID*HID],  g_wkl[HID*HID];
__device__ __nv_bfloat16 g_wvh[HID*HID],  g_wvl[HID*HID];
__device__ __nv_bfloat16 g_woh[HID*HID],  g_wol[HID*HID];
__device__ __nv_bfloat16 g_wih[HID*INTER], g_wil[HID*INTER];
__device__ __nv_bfloat16 g_wdh[HID*INTER], g_wdl[HID*INTER];

// ---------------- helpers --------------------------------------------------------
__device__ __forceinline__ float gelu_exact(float x) {
    return 0.5f * x * (1.0f + erff(x * 0.7071067811865476f));
}

__device__ __forceinline__ void ldsm4(uint32_t* r, uint32_t addr) {
    asm volatile("ldmatrix.sync.aligned.m8n8.x4.shared.b16 {%0,%1,%2,%3},[%4];\n"
                 : "=r"(r[0]), "=r"(r[1]), "=r"(r[2]), "=r"(r[3]) : "r"(addr));
}

__device__ __forceinline__ void mma16816(float* d, const uint32_t* a, uint32_t b0, uint32_t b1) {
    asm volatile(
        "mma.sync.aligned.m16n8k16.row.col.f32.bf16.bf16.f32 "
        "{%0,%1,%2,%3},{%4,%5,%6,%7},{%8,%9},{%0,%1,%2,%3};\n"
        : "+f"(d[0]), "+f"(d[1]), "+f"(d[2]), "+f"(d[3])
        : "r"(a[0]), "r"(a[1]), "r"(a[2]), "r"(a[3]), "r"(b0), "r"(b1));
}

// ---------------- split / transpose-split conversions ----------------------------
__global__ __launch_bounds__(256)
void split_kernel(const float* __restrict__ x, __nv_bfloat16* __restrict__ hi,
                  __nv_bfloat16* __restrict__ lo, int n4)  // n4 = n/4
{
    int i = blockIdx.x * 256 + threadIdx.x;
    if (i >= n4) return;
    float4 v = ((const float4*)x)[i];
    __nv_bfloat16 h0 = __float2bfloat16(v.x), h1 = __float2bfloat16(v.y);
    __nv_bfloat16 h2 = __float2bfloat16(v.z), h3 = __float2bfloat16(v.w);
    __nv_bfloat162 hv0; hv0.x = h0; hv0.y = h1;
    __nv_bfloat162 hv1; hv1.x = h2; hv1.y = h3;
    ((__nv_bfloat162*)hi)[2*i]   = hv0;
    ((__nv_bfloat162*)hi)[2*i+1] = hv1;
    __nv_bfloat162 lv0, lv1;
    lv0.x = __float2bfloat16(v.x - __bfloat162float(h0));
    lv0.y = __float2bfloat16(v.y - __bfloat162float(h1));
    lv1.x = __float2bfloat16(v.z - __bfloat162float(h2));
    lv1.y = __float2bfloat16(v.w - __bfloat162float(h3));
    ((__nv_bfloat162*)lo)[2*i]   = lv0;
    ((__nv_bfloat162*)lo)[2*i+1] = lv1;
}

// W[K][N] -> T[N][K] split into hi/lo
__global__ __launch_bounds__(256)
void tsplit_kernel(const float* __restrict__ W, __nv_bfloat16* __restrict__ Th,
                   __nv_bfloat16* __restrict__ Tl, int K, int N)
{
    __shared__ float tile[32][33];
    int n0 = blockIdx.x * 32;
    int k0 = blockIdx.y * 32;
    int tx = threadIdx.x & 31;
    int ty = threadIdx.x >> 5;   // 0..7
    #pragma unroll
    for (int r = 0; r < 4; r++)
        tile[ty + 8*r][tx] = W[(size_t)(k0 + ty + 8*r) * N + n0 + tx];
    __syncthreads();
    #pragma unroll
    for (int r = 0; r < 4; r++) {
        float v = tile[tx][ty + 8*r];
        __nv_bfloat16 h = __float2bfloat16(v);
        size_t idx = (size_t)(n0 + ty + 8*r) * K + k0 + tx;
        Th[idx] = h;
        Tl[idx] = __float2bfloat16(v - __bfloat162float(h));
    }
}

// ---------------- bf16x3 MMA GEMM: C[M,N] = A[M,K] * Bt[N,K]^T ------------------
// epi: 0 = bias, 1 = bias+residual, 2 = bias+gelu
#define SA 24
#define PLANE (128*SA)   // bf16 elems per plane (6144 bytes)

__global__ __launch_bounds__(256)
void mma_gemm(const __nv_bfloat16* __restrict__ Ah, const __nv_bfloat16* __restrict__ Al,
              const __nv_bfloat16* __restrict__ Bh, const __nv_bfloat16* __restrict__ Bl,
              const float* __restrict__ bias, const float* __restrict__ res,
              float* __restrict__ C, int M, int N, int K, int epi)
{
    __shared__ __align__(16) __nv_bfloat16 sA[2*2*PLANE];   // [buf][plane]
    __shared__ __align__(16) __nv_bfloat16 sB[2*2*PLANE];

    int tid = threadIdx.x, lane = tid & 31, w = tid >> 5;
    int row0 = blockIdx.y * 128, col0 = blockIdx.x * 128;
    int wm = (w >> 1) * 32, wn = (w & 1) * 64;

    // global tile load mapping: 128 rows x 16 k, one uint4 (8 bf16) per thread/plane
    int lr = tid >> 1;          // 0..127
    int lh = (tid & 1) * 8;     // 0 or 8
    bool avalid = (row0 + lr) < M;
    const __nv_bfloat16* gAh = Ah + (size_t)(row0 + lr) * K + lh;
    const __nv_bfloat16* gAl = Al + (size_t)(row0 + lr) * K + lh;
    const __nv_bfloat16* gBh = Bh + (size_t)(col0 + lr) * K + lh;
    const __nv_bfloat16* gBl = Bl + (size_t)(col0 + lr) * K + lh;
    int st = lr * SA + lh;      // smem elem offset within plane

    uint32_t sAu = (uint32_t)__cvta_generic_to_shared(sA);
    uint32_t sBu = (uint32_t)__cvta_generic_to_shared(sB);

    // ldmatrix per-lane row/col offsets
    int arow_l = (lane & 7) + ((lane >> 3) & 1) * 8;
    int acol_l = (lane >> 4) * 8;
    int brow_l = (lane & 7) + ((lane >> 4) & 1) * 8;
    int bcol_l = ((lane >> 3) & 1) * 8;

    float acc[2][8][4];
    #pragma unroll
    for (int i = 0; i < 2; i++)
        #pragma unroll
        for (int j = 0; j < 8; j++)
            #pragma unroll
            for (int r = 0; r < 4; r++) acc[i][j][r] = 0.0f;

    const uint4 zero4 = make_uint4(0, 0, 0, 0);

    // prologue: tile 0 -> buf 0
    {
        uint4 pah = avalid ? *(const uint4*)gAh : zero4;
        uint4 pal = avalid ? *(const uint4*)gAl : zero4;
        uint4 pbh = *(const uint4*)gBh;
        uint4 pbl = *(const uint4*)gBl;
        *(uint4*)&sA[0*PLANE + st] = pah;
        *(uint4*)&sA[1*PLANE + st] = pal;
        *(uint4*)&sB[0*PLANE + st] = pbh;
        *(uint4*)&sB[1*PLANE + st] = pbl;
    }
    __syncthreads();

    int NT = K / 16;
    for (int t = 0; t < NT; t++) {
        int cur = t & 1;
        uint4 pah, pal, pbh, pbl;
        if (t + 1 < NT) {
            size_t off = (size_t)(t + 1) * 16;
            pah = avalid ? *(const uint4*)(gAh + off) : zero4;
            pal = avalid ? *(const uint4*)(gAl + off) : zero4;
            pbh = *(const uint4*)(gBh + off);
            pbl = *(const uint4*)(gBl + off);
        }

        // A fragments (hi, lo) for 2 m-tiles
        uint32_t aF[2][2][4];
        #pragma unroll
        for (int p = 0; p < 2; p++)
            #pragma unroll
            for (int i = 0; i < 2; i++) {
                uint32_t ad = sAu + ((cur*2 + p)*PLANE + (wm + 16*i + arow_l)*SA + acol_l)*2;
                ldsm4(aF[p][i], ad);
            }

        #pragma unroll
        for (int jj = 0; jj < 4; jj++) {
            uint32_t bh[4], bl[4];
            uint32_t bd0 = sBu + ((cur*2 + 0)*PLANE + (wn + 16*jj + brow_l)*SA + bcol_l)*2;
            uint32_t bd1 = sBu + ((cur*2 + 1)*PLANE + (wn + 16*jj + brow_l)*SA + bcol_l)*2;
            ldsm4(bh, bd0);
            ldsm4(bl, bd1);
            #pragma unroll
            for (int i = 0; i < 2; i++) {
                mma16816(acc[i][2*jj],   aF[0][i], bh[0], bh[1]);   // hi*hi
                mma16816(acc[i][2*jj+1], aF[0][i], bh[2], bh[3]);
                mma16816(acc[i][2*jj],   aF[0][i], bl[0], bl[1]);   // hi*lo
                mma16816(acc[i][2*jj+1], aF[0][i], bl[2], bl[3]);
                mma16816(acc[i][2*jj],   aF[1][i], bh[0], bh[1]);   // lo*hi
                mma16816(acc[i][2*jj+1], aF[1][i], bh[2], bh[3]);
            }
        }

        if (t + 1 < NT) {
            int nx = cur ^ 1;
            *(uint4*)&sA[(nx*2 + 0)*PLANE + st] = pah;
            *(uint4*)&sA[(nx*2 + 1)*PLANE + st] = pal;
            *(uint4*)&sB[(nx*2 + 0)*PLANE + st] = pbh;
            *(uint4*)&sB[(nx*2 + 1)*PLANE + st] = pbl;
        }
        __syncthreads();
    }

    // epilogue
    #pragma unroll
    for (int i = 0; i < 2; i++) {
        int r = row0 + wm + 16*i + (lane >> 2);
        #pragma unroll
        for (int j = 0; j < 8; j++) {
            int c = col0 + wn + 8*j + (lane & 3)*2;
            float2 bv = *(const float2*)&bias[c];
            float o0 = acc[i][j][0] + bv.x, o1 = acc[i][j][1] + bv.y;
            float o2 = acc[i][j][2] + bv.x, o3 = acc[i][j][3] + bv.y;
            if (epi == 2) {
                o0 = gelu_exact(o0); o1 = gelu_exact(o1);
                o2 = gelu_exact(o2); o3 = gelu_exact(o3);
            }
            if (r < M) {
                if (epi == 1) {
                    float2 rv = *(const float2*)&res[(size_t)r*N + c];
                    o0 += rv.x; o1 += rv.y;
                }
                float2 ov; ov.x = o0; ov.y = o1;
                *(float2*)&C[(size_t)r*N + c] = ov;
            }
            if (r + 8 < M) {
                if (epi == 1) {
                    float2 rv = *(const float2*)&res[(size_t)(r+8)*N + c];
                    o2 += rv.x; o3 += rv.y;
                }
                float2 ov; ov.x = o2; ov.y = o3;
                *(float2*)&C[(size_t)(r+8)*N + c] = ov;
            }
        }
    }
}

// ---------------- Flash attention (fp32), 64x64 tiles ---------------------------
__device__ __forceinline__ float lead_bias(int r, int c) {
    if (r == 0) return (c >= 1 && c < NUM_LEAD + 1) ? -99999.0f : 0.0f;
    if (r <= NUM_LEAD) {
        int st = NUM_LEAD + 1 + PATCHES * (r - 1);
        return (c >= st && c < st + PATCHES) ? 0.0f : -99999.0f;
    }
    return 0.0f;
}

__global__ __launch_bounds__(256)
void flash_kernel(const float* __restrict__ q, const float* __restrict__ k,
                  const float* __restrict__ v, const float* __restrict__ amask,
                  float* __restrict__ ctx)
{
    __shared__ float Qt [64*64];
    __shared__ float KPs[64*64];
    __shared__ float Vs [64*64];

    int tid = threadIdx.x;
    int qt  = blockIdx.x;
    int h   = blockIdx.y;
    int b   = blockIdx.z;
    int q0  = qt * 64;
    int ty  = tid >> 4;
    int tx  = tid & 15;

    {
        int r  = tid >> 2;
        int c0 = (tid & 3) * 16;
        int gr = q0 + r;
        const float* src = q + (size_t)(b*SEQ + (gr < SEQ ? gr : SEQ-1))*HID + h*DH + c0;
        #pragma unroll
        for (int i = 0; i < 16; i += 4) {
            float4 val = (gr < SEQ) ? *(const float4*)(src + i) : make_float4(0,0,0,0);
            Qt[(c0+i+0)*64 + r] = val.x;
            Qt[(c0+i+1)*64 + r] = val.y;
            Qt[(c0+i+2)*64 + r] = val.z;
            Qt[(c0+i+3)*64 + r] = val.w;
        }
    }

    float o[4][4];
    #pragma unroll
    for (int i = 0; i < 4; i++)
        #pragma unroll
        for (int j = 0; j < 4; j++) o[i][j] = 0.0f;
    float m[4] = {-1e30f,-1e30f,-1e30f,-1e30f};
    float l[4] = {0,0,0,0};

    int ntile = (SEQ + 63) / 64;
    for (int t = 0; t < ntile; t++) {
        int k0 = t * 64;
        __syncthreads();
        {
            int r  = tid >> 2;
            int c0 = (tid & 3) * 16;
            int gsr = k0 + r;
            bool ok = gsr < SEQ;
            const float* ks = k + (size_t)(b*SEQ + (ok ? gsr : SEQ-1))*HID + h*DH + c0;
            const float* vs = v + (size_t)(b*SEQ + (ok ? gsr : SEQ-1))*HID + h*DH + c0;
            #pragma unroll
            for (int i = 0; i < 16; i += 4) {
                float4 kv = ok ? *(const float4*)(ks + i) : make_float4(0,0,0,0);
                float4 vv = ok ? *(const float4*)(vs + i) : make_float4(0,0,0,0);
                KPs[(c0+i+0)*64 + r] = kv.x;
                KPs[(c0+i+1)*64 + r] = kv.y;
                KPs[(c0+i+2)*64 + r] = kv.z;
                KPs[(c0+i+3)*64 + r] = kv.w;
                *(float4*)&Vs[r*64 + c0+i] = vv;
            }
        }
        __syncthreads();

        float acc[4][4];
        #pragma unroll
        for (int i = 0; i < 4; i++)
            #pragma unroll
            for (int j = 0; j < 4; j++) acc[i][j] = 0.0f;
        #pragma unroll 16
        for (int kk = 0; kk < 64; kk++) {
            float4 qv = *(const float4*)&Qt [kk*64 + ty*4];
            float4 kv = *(const float4*)&KPs[kk*64 + tx*4];
            float qa[4] = {qv.x,qv.y,qv.z,qv.w};
            float ka[4] = {kv.x,kv.y,kv.z,kv.w};
            #pragma unroll
            for (int i = 0; i < 4; i++)
                #pragma unroll
                for (int j = 0; j < 4; j++)
                    acc[i][j] += qa[i] * ka[j];
        }

        int gcb = k0 + tx*4;
        float amv[4];
        #pragma unroll
        for (int j = 0; j < 4; j++)
            amv[j] = (gcb + j < SEQ) ? amask[(size_t)b*SEQ + gcb + j] : 0.0f;
        #pragma unroll
        for (int i = 0; i < 4; i++) {
            int gr = q0 + ty*4 + i;
            #pragma unroll
            for (int j = 0; j < 4; j++) {
                int gc = gcb + j;
                float sc = acc[i][j] * 0.125f + amv[j];
                if (q0 == 0) sc += lead_bias(gr, gc);
                if (gc >= SEQ) sc = -1e30f;
                acc[i][j] = sc;
            }
        }

        #pragma unroll
        for (int i = 0; i < 4; i++) {
            float mt = fmaxf(fmaxf(acc[i][0], acc[i][1]), fmaxf(acc[i][2], acc[i][3]));
            #pragma unroll
            for (int off = 8; off >= 1; off >>= 1)
                mt = fmaxf(mt, __shfl_xor_sync(0xffffffffu, mt, off));
            float mn = fmaxf(m[i], mt);
            float corr = __expf(m[i] - mn);
            m[i] = mn;
            float rs = 0.0f;
            #pragma unroll
            for (int j = 0; j < 4; j++) {
                acc[i][j] = __expf(acc[i][j] - mn);
                rs += acc[i][j];
            }
            #pragma unroll
            for (int off = 8; off >= 1; off >>= 1)
                rs += __shfl_xor_sync(0xffffffffu, rs, off);
            l[i] = l[i] * corr + rs;
            #pragma unroll
            for (int j = 0; j < 4; j++) o[i][j] *= corr;
        }

        __syncthreads();
        #pragma unroll
        for (int i = 0; i < 4; i++) {
            float4 p4 = make_float4(acc[i][0], acc[i][1], acc[i][2], acc[i][3]);
            *(float4*)&KPs[(ty*4 + i)*64 + tx*4] = p4;
        }
        __syncthreads();

        #pragma unroll 4
        for (int kk = 0; kk < 64; kk += 4) {
            float4 pv[4];
            #pragma unroll
            for (int i = 0; i < 4; i++)
                pv[i] = *(const float4*)&KPs[(ty*4 + i)*64 + kk];
            #pragma unroll
            for (int s = 0; s < 4; s++) {
                float4 vv = *(const float4*)&Vs[(kk + s)*64 + tx*4];
                float pvs[4] = { (&pv[0].x)[s], (&pv[1].x)[s], (&pv[2].x)[s], (&pv[3].x)[s] };
                #pragma unroll
                for (int i = 0; i < 4; i++) {
                    o[i][0] += pvs[i] * vv.x;
                    o[i][1] += pvs[i] * vv.y;
                    o[i][2] += pvs[i] * vv.z;
                    o[i][3] += pvs[i] * vv.w;
                }
            }
        }
    }

    #pragma unroll
    for (int i = 0; i < 4; i++) {
        int gr = q0 + ty*4 + i;
        if (gr >= SEQ) continue;
        float inv = 1.0f / l[i];
        float4 o4 = make_float4(o[i][0]*inv, o[i][1]*inv, o[i][2]*inv, o[i][3]*inv);
        *(float4*)&ctx[(size_t)(b*SEQ + gr)*HID + h*DH + tx*4] = o4;
    }
}

// ---------------- LayerNorm (two-pass, eps 1e-12) -------------------------------
__global__ __launch_bounds__(256)
void ln_kernel(const float* __restrict__ x, const float* __restrict__ g,
               const float* __restrict__ bta, float* __restrict__ y)
{
    __shared__ float red[8];
    int row = blockIdx.x;
    int tid = threadIdx.x;
    const float* xr = x + (size_t)row * HID;

    float v[3];
    float s = 0.0f;
    #pragma unroll
    for (int i = 0; i < 3; i++) { v[i] = xr[tid + i*256]; s += v[i]; }

    #pragma unroll
    for (int off = 16; off >= 1; off >>= 1) s += __shfl_xor_sync(0xffffffffu, s, off);
    if ((tid & 31) == 0) red[tid >> 5] = s;
    __syncthreads();
    s = red[0]+red[1]+red[2]+red[3]+red[4]+red[5]+red[6]+red[7];
    float mean = s * (1.0f / HID);
    __syncthreads();

    float s2 = 0.0f;
    #pragma unroll
    for (int i = 0; i < 3; i++) { float d = v[i] - mean; s2 += d * d; }
    #pragma unroll
    for (int off = 16; off >= 1; off >>= 1) s2 += __shfl_xor_sync(0xffffffffu, s2, off);
    if ((tid & 31) == 0) red[tid >> 5] = s2;
    __syncthreads();
    s2 = red[0]+red[1]+red[2]+red[3]+red[4]+red[5]+red[6]+red[7];
    float rstd = rsqrtf(s2 * (1.0f / HID) + 1e-12f);

    #pragma unroll
    for (int i = 0; i < 3; i++) {
        int c = tid + i*256;
        y[(size_t)row*HID + c] = g[c] * (v[i] - mean) * rstd + bta[c];
    }
}

// ---------------- launch --------------------------------------------------------
extern "C" void kernel_launch(void* const* d_in, const int* in_sizes, int n_in,
                              void* d_out, int out_size)
{
    const float* X     = (const float*)d_in[0];
    const float* amask = (const float*)d_in[1];
    const float* Wq = (const float*)d_in[2];  const float* bq = (const float*)d_in[3];
    const float* Wk = (const float*)d_in[4];  const float* bk = (const float*)d_in[5];
    const float* Wv = (const float*)d_in[6];  const float* bv = (const float*)d_in[7];
    const float* Wo = (const float*)d_in[8];  const float* bo = (const float*)d_in[9];
    const float* g1 = (const float*)d_in[10]; const float* b1 = (const float*)d_in[11];
    const float* Wi = (const float*)d_in[12]; const float* bi = (const float*)d_in[13];
    const float* Wd = (const float*)d_in[14]; const float* bd = (const float*)d_in[15];
    const float* g2 = (const float*)d_in[16]; const float* b2 = (const float*)d_in[17];

    float *q, *k, *v, *ctx, *t1, *attn, *inter;
    cudaGetSymbolAddress((void**)&q,     g_q);
    cudaGetSymbolAddress((void**)&k,     g_k);
    cudaGetSymbolAddress((void**)&v,     g_v);
    cudaGetSymbolAddress((void**)&ctx,   g_ctx);
    cudaGetSymbolAddress((void**)&t1,    g_t1);
    cudaGetSymbolAddress((void**)&attn,  g_attn);
    cudaGetSymbolAddress((void**)&inter, g_int);

    __nv_bfloat16 *ah, *al;
    __nv_bfloat16 *wqh, *wql, *wkh, *wkl, *wvh, *wvl, *woh, *wol, *wih, *wil, *wdh, *wdl;
    cudaGetSymbolAddress((void**)&ah,  g_ah);
    cudaGetSymbolAddress((void**)&al,  g_al);
    cudaGetSymbolAddress((void**)&wqh, g_wqh); cudaGetSymbolAddress((void**)&wql, g_wql);
    cudaGetSymbolAddress((void**)&wkh, g_wkh); cudaGetSymbolAddress((void**)&wkl, g_wkl);
    cudaGetSymbolAddress((void**)&wvh, g_wvh); cudaGetSymbolAddress((void**)&wvl, g_wvl);
    cudaGetSymbolAddress((void**)&woh, g_woh); cudaGetSymbolAddress((void**)&wol, g_wol);
    cudaGetSymbolAddress((void**)&wih, g_wih); cudaGetSymbolAddress((void**)&wil, g_wil);
    cudaGetSymbolAddress((void**)&wdh, g_wdh); cudaGetSymbolAddress((void**)&wdl, g_wdl);

    dim3 blk(256);
    const int MB = (MROWS + 127) / 128;      // 76
    dim3 gGH(HID/128, MB);                    // GEMM N=768
    dim3 gGI(INTER/128, MB);                  // GEMM N=3072

    // weight transposed splits (per-launch, deterministic)
    dim3 tH(HID/32, HID/32), tI(INTER/32, HID/32), tD(HID/32, INTER/32);
    tsplit_kernel<<<tH, blk>>>(Wq, wqh, wql, HID, HID);
    tsplit_kernel<<<tH, blk>>>(Wk, wkh, wkl, HID, HID);
    tsplit_kernel<<<tH, blk>>>(Wv, wvh, wvl, HID, HID);
    tsplit_kernel<<<tH, blk>>>(Wo, woh, wol, HID, HID);
    tsplit_kernel<<<tI, blk>>>(Wi, wih, wil, HID, INTER);
    tsplit_kernel<<<tD, blk>>>(Wd, wdh, wdl, INTER, HID);

    int nX4 = (MROWS*HID)/4;
    int nI4 = (MROWS*INTER)/4;

    // QKV
    split_kernel<<<(nX4 + 255)/256, blk>>>(X, ah, al, nX4);
    mma_gemm<<<gGH, blk>>>(ah, al, wqh, wql, bq, nullptr, q, MROWS, HID, HID, 0);
    mma_gemm<<<gGH, blk>>>(ah, al, wkh, wkl, bk, nullptr, k, MROWS, HID, HID, 0);
    mma_gemm<<<gGH, blk>>>(ah, al, wvh, wvl, bv, nullptr, v, MROWS, HID, HID, 0);

    // attention
    dim3 gF((SEQ + 63)/64, NH, BATCH);
    flash_kernel<<<gF, blk>>>(q, k, v, amask, ctx);

    // O-proj + residual + LN
    split_kernel<<<(nX4 + 255)/256, blk>>>(ctx, ah, al, nX4);
    mma_gemm<<<gGH, blk>>>(ah, al, woh, wol, bo, X, t1, MROWS, HID, HID, 1);
    ln_kernel<<<MROWS, blk>>>(t1, g1, b1, attn);

    // FFN
    split_kernel<<<(nX4 + 255)/256, blk>>>(attn, ah, al, nX4);
    mma_gemm<<<gGI, blk>>>(ah, al, wih, wil, bi, nullptr, inter, MROWS, INTER, HID, 2);
    split_kernel<<<(nI4 + 255)/256, blk>>>(inter, ah, al, nI4);
    mma_gemm<<<gGH, blk>>>(ah, al, wdh, wdl, bd, attn, t1, MROWS, HID, INTER, 1);
    ln_kernel<<<MROWS, blk>>>(t1, g2, b2, (float*)d_out);
}

// round 5
// speedup vs baseline: 2.9264x; 1.4577x over previous
#include <cuda_runtime.h>
#include <cuda_bf16.h>
#include <math.h>
#include <stdint.h>

#define BATCH 8
#define SEQ   1213
#define HID   768
#define NH    12
#define DH    64
#define INTER 3072
#define MROWS (BATCH*SEQ)   // 9704
#define NUM_LEAD 12
#define PATCHES 100

// epilogue mode bits
#define EPI_RES  1
#define EPI_GELU 2
#define EPI_F32  4
#define EPI_BF16 8

// ---------------- scratch (device globals) ---------------------------------------
__device__ float g_t1  [(size_t)MROWS*HID];
__device__ float g_attn[(size_t)MROWS*HID];

__device__ __nv_bfloat16 g_ah[(size_t)MROWS*INTER];
__device__ __nv_bfloat16 g_al[(size_t)MROWS*INTER];
__device__ __nv_bfloat16 g_bh[(size_t)MROWS*INTER];
__device__ __nv_bfloat16 g_bl[(size_t)MROWS*INTER];
__device__ __nv_bfloat16 g_qh[(size_t)MROWS*HID], g_ql[(size_t)MROWS*HID];
__device__ __nv_bfloat16 g_kh[(size_t)MROWS*HID], g_kl[(size_t)MROWS*HID];
__device__ __nv_bfloat16 g_vh[(size_t)MROWS*HID], g_vl[(size_t)MROWS*HID];

__device__ __nv_bfloat16 g_wqh[HID*HID],  g_wql[HID*HID];
__device__ __nv_bfloat16 g_wkh[HID*HID],  g_wkl[HID*HID];
__device__ __nv_bfloat16 g_wvh[HID*HID],  g_wvl[HID*HID];
__device__ __nv_bfloat16 g_woh[HID*HID],  g_wol[HID*HID];
__device__ __nv_bfloat16 g_wih[HID*INTER], g_wil[HID*INTER];
__device__ __nv_bfloat16 g_wdh[HID*INTER], g_wdl[HID*INTER];

// ---------------- helpers --------------------------------------------------------
__device__ __forceinline__ float gelu_exact(float x) {
    return 0.5f * x * (1.0f + erff(x * 0.7071067811865476f));
}

__device__ __forceinline__ void ldsm4(uint32_t* r, uint32_t addr) {
    asm volatile("ldmatrix.sync.aligned.m8n8.x4.shared.b16 {%0,%1,%2,%3},[%4];\n"
                 : "=r"(r[0]), "=r"(r[1]), "=r"(r[2]), "=r"(r[3]) : "r"(addr));
}
__device__ __forceinline__ void ldsm4t(uint32_t* r, uint32_t addr) {
    asm volatile("ldmatrix.sync.aligned.m8n8.x4.trans.shared.b16 {%0,%1,%2,%3},[%4];\n"
                 : "=r"(r[0]), "=r"(r[1]), "=r"(r[2]), "=r"(r[3]) : "r"(addr));
}
__device__ __forceinline__ void mma16816(float* d, const uint32_t* a, uint32_t b0, uint32_t b1) {
    asm volatile(
        "mma.sync.aligned.m16n8k16.row.col.f32.bf16.bf16.f32 "
        "{%0,%1,%2,%3},{%4,%5,%6,%7},{%8,%9},{%0,%1,%2,%3};\n"
        : "+f"(d[0]), "+f"(d[1]), "+f"(d[2]), "+f"(d[3])
        : "r"(a[0]), "r"(a[1]), "r"(a[2]), "r"(a[3]), "r"(b0), "r"(b1));
}
__device__ __forceinline__ uint32_t packbf2(float a, float b) {
    __nv_bfloat162 h = __floats2bfloat162_rn(a, b);
    return *(uint32_t*)&h;
}

// ---------------- split X -> bf16 hi/lo -----------------------------------------
__global__ __launch_bounds__(256)
void split_kernel(const float* __restrict__ x, __nv_bfloat16* __restrict__ hi,
                  __nv_bfloat16* __restrict__ lo, int n4)
{
    int i = blockIdx.x * 256 + threadIdx.x;
    if (i >= n4) return;
    float4 v = ((const float4*)x)[i];
    __nv_bfloat16 h0 = __float2bfloat16(v.x), h1 = __float2bfloat16(v.y);
    __nv_bfloat16 h2 = __float2bfloat16(v.z), h3 = __float2bfloat16(v.w);
    __nv_bfloat162 hv0; hv0.x = h0; hv0.y = h1;
    __nv_bfloat162 hv1; hv1.x = h2; hv1.y = h3;
    ((__nv_bfloat162*)hi)[2*i]   = hv0;
    ((__nv_bfloat162*)hi)[2*i+1] = hv1;
    __nv_bfloat162 lv0, lv1;
    lv0.x = __float2bfloat16(v.x - __bfloat162float(h0));
    lv0.y = __float2bfloat16(v.y - __bfloat162float(h1));
    lv1.x = __float2bfloat16(v.z - __bfloat162float(h2));
    lv1.y = __float2bfloat16(v.w - __bfloat162float(h3));
    ((__nv_bfloat162*)lo)[2*i]   = lv0;
    ((__nv_bfloat162*)lo)[2*i+1] = lv1;
}

// ---------------- all-weights transpose-split (ONE launch) ----------------------
__device__ __forceinline__
void tsplit_tile(const float* __restrict__ W, __nv_bfloat16* __restrict__ Th,
                 __nv_bfloat16* __restrict__ Tl, int K, int N, int bx, int by)
{
    __shared__ float tile[32][33];
    int n0 = bx * 32, k0 = by * 32;
    int tx = threadIdx.x & 31, ty = threadIdx.x >> 5;
    #pragma unroll
    for (int r = 0; r < 4; r++)
        tile[ty + 8*r][tx] = W[(size_t)(k0 + ty + 8*r) * N + n0 + tx];
    __syncthreads();
    #pragma unroll
    for (int r = 0; r < 4; r++) {
        float v = tile[tx][ty + 8*r];
        __nv_bfloat16 h = __float2bfloat16(v);
        size_t idx = (size_t)(n0 + ty + 8*r) * K + k0 + tx;
        Th[idx] = h;
        Tl[idx] = __float2bfloat16(v - __bfloat162float(h));
    }
}

__global__ __launch_bounds__(256)
void tsplit_all(const float* Wq, const float* Wk, const float* Wv, const float* Wo,
                const float* Wi, const float* Wd,
                __nv_bfloat16* wqh, __nv_bfloat16* wql, __nv_bfloat16* wkh, __nv_bfloat16* wkl,
                __nv_bfloat16* wvh, __nv_bfloat16* wvl, __nv_bfloat16* woh, __nv_bfloat16* wol,
                __nv_bfloat16* wih, __nv_bfloat16* wil, __nv_bfloat16* wdh, __nv_bfloat16* wdl)
{
    int id = blockIdx.x;
    // Wq/Wk/Wv/Wo: 24x24=576 tiles each; Wi: 96x24=2304; Wd: 24x96=2304
    if (id < 2304) {
        int r = id / 576, l = id % 576;
        const float* W = (r==0)?Wq:(r==1)?Wk:(r==2)?Wv:Wo;
        __nv_bfloat16* Th = (r==0)?wqh:(r==1)?wkh:(r==2)?wvh:woh;
        __nv_bfloat16* Tl = (r==0)?wql:(r==1)?wkl:(r==2)?wvl:wol;
        tsplit_tile(W, Th, Tl, HID, HID, l % 24, l / 24);
    } else if (id < 4608) {
        int l = id - 2304;
        tsplit_tile(Wi, wih, wil, HID, INTER, l % 96, l / 96);
    } else {
        int l = id - 4608;
        tsplit_tile(Wd, wdh, wdl, INTER, HID, l % 24, l / 24);
    }
}

// ---------------- bf16x3 MMA GEMM -----------------------------------------------
#define SA 24
#define PLANE (128*SA)

__global__ __launch_bounds__(256)
void mma_gemm(const __nv_bfloat16* __restrict__ Ah, const __nv_bfloat16* __restrict__ Al,
              const __nv_bfloat16* __restrict__ Bh, const __nv_bfloat16* __restrict__ Bl,
              const float* __restrict__ bias, const float* __restrict__ res,
              float* __restrict__ C,
              __nv_bfloat16* __restrict__ Ch, __nv_bfloat16* __restrict__ Cl,
              int M, int N, int K, int epi)
{
    __shared__ __align__(16) __nv_bfloat16 sA[2*2*PLANE];
    __shared__ __align__(16) __nv_bfloat16 sB[2*2*PLANE];

    int tid = threadIdx.x, lane = tid & 31, w = tid >> 5;
    int row0 = blockIdx.y * 128, col0 = blockIdx.x * 128;
    int wm = (w >> 1) * 32, wn = (w & 1) * 64;

    int lr = tid >> 1;
    int lh = (tid & 1) * 8;
    bool avalid = (row0 + lr) < M;
    const __nv_bfloat16* gAh = Ah + (size_t)(row0 + lr) * K + lh;
    const __nv_bfloat16* gAl = Al + (size_t)(row0 + lr) * K + lh;
    const __nv_bfloat16* gBh = Bh + (size_t)(col0 + lr) * K + lh;
    const __nv_bfloat16* gBl = Bl + (size_t)(col0 + lr) * K + lh;
    int st = lr * SA + lh;

    uint32_t sAu = (uint32_t)__cvta_generic_to_shared(sA);
    uint32_t sBu = (uint32_t)__cvta_generic_to_shared(sB);

    int arow_l = (lane & 7) + ((lane >> 3) & 1) * 8;
    int acol_l = (lane >> 4) * 8;
    int brow_l = (lane & 7) + ((lane >> 4) & 1) * 8;
    int bcol_l = ((lane >> 3) & 1) * 8;

    float acc[2][8][4];
    #pragma unroll
    for (int i = 0; i < 2; i++)
        #pragma unroll
        for (int j = 0; j < 8; j++)
            #pragma unroll
            for (int r = 0; r < 4; r++) acc[i][j][r] = 0.0f;

    const uint4 zero4 = make_uint4(0, 0, 0, 0);
    {
        uint4 pah = avalid ? *(const uint4*)gAh : zero4;
        uint4 pal = avalid ? *(const uint4*)gAl : zero4;
        uint4 pbh = *(const uint4*)gBh;
        uint4 pbl = *(const uint4*)gBl;
        *(uint4*)&sA[0*PLANE + st] = pah;
        *(uint4*)&sA[1*PLANE + st] = pal;
        *(uint4*)&sB[0*PLANE + st] = pbh;
        *(uint4*)&sB[1*PLANE + st] = pbl;
    }
    __syncthreads();

    int NT = K / 16;
    for (int t = 0; t < NT; t++) {
        int cur = t & 1;
        uint4 pah, pal, pbh, pbl;
        if (t + 1 < NT) {
            size_t off = (size_t)(t + 1) * 16;
            pah = avalid ? *(const uint4*)(gAh + off) : zero4;
            pal = avalid ? *(const uint4*)(gAl + off) : zero4;
            pbh = *(const uint4*)(gBh + off);
            pbl = *(const uint4*)(gBl + off);
        }

        uint32_t aF[2][2][4];
        #pragma unroll
        for (int p = 0; p < 2; p++)
            #pragma unroll
            for (int i = 0; i < 2; i++) {
                uint32_t ad = sAu + ((cur*2 + p)*PLANE + (wm + 16*i + arow_l)*SA + acol_l)*2;
                ldsm4(aF[p][i], ad);
            }

        #pragma unroll
        for (int jj = 0; jj < 4; jj++) {
            uint32_t bh[4], bl[4];
            ldsm4(bh, sBu + ((cur*2 + 0)*PLANE + (wn + 16*jj + brow_l)*SA + bcol_l)*2);
            ldsm4(bl, sBu + ((cur*2 + 1)*PLANE + (wn + 16*jj + brow_l)*SA + bcol_l)*2);
            #pragma unroll
            for (int i = 0; i < 2; i++) {
                mma16816(acc[i][2*jj],   aF[0][i], bh[0], bh[1]);
                mma16816(acc[i][2*jj+1], aF[0][i], bh[2], bh[3]);
                mma16816(acc[i][2*jj],   aF[0][i], bl[0], bl[1]);
                mma16816(acc[i][2*jj+1], aF[0][i], bl[2], bl[3]);
                mma16816(acc[i][2*jj],   aF[1][i], bh[0], bh[1]);
                mma16816(acc[i][2*jj+1], aF[1][i], bh[2], bh[3]);
            }
        }

        if (t + 1 < NT) {
            int nx = cur ^ 1;
            *(uint4*)&sA[(nx*2 + 0)*PLANE + st] = pah;
            *(uint4*)&sA[(nx*2 + 1)*PLANE + st] = pal;
            *(uint4*)&sB[(nx*2 + 0)*PLANE + st] = pbh;
            *(uint4*)&sB[(nx*2 + 1)*PLANE + st] = pbl;
        }
        __syncthreads();
    }

    // epilogue
    #pragma unroll
    for (int i = 0; i < 2; i++) {
        int r = row0 + wm + 16*i + (lane >> 2);
        #pragma unroll
        for (int j = 0; j < 8; j++) {
            int c = col0 + wn + 8*j + (lane & 3)*2;
            float2 bv = *(const float2*)&bias[c];
            float o0 = acc[i][j][0] + bv.x, o1 = acc[i][j][1] + bv.y;
            float o2 = acc[i][j][2] + bv.x, o3 = acc[i][j][3] + bv.y;
            if (epi & EPI_GELU) {
                o0 = gelu_exact(o0); o1 = gelu_exact(o1);
                o2 = gelu_exact(o2); o3 = gelu_exact(o3);
            }
            if (r < M) {
                if (epi & EPI_RES) {
                    float2 rv = *(const float2*)&res[(size_t)r*N + c];
                    o0 += rv.x; o1 += rv.y;
                }
                if (epi & EPI_F32) {
                    float2 ov; ov.x = o0; ov.y = o1;
                    *(float2*)&C[(size_t)r*N + c] = ov;
                }
                if (epi & EPI_BF16) {
                    __nv_bfloat162 hv; hv.x = __float2bfloat16(o0); hv.y = __float2bfloat16(o1);
                    *(__nv_bfloat162*)&Ch[(size_t)r*N + c] = hv;
                    __nv_bfloat162 lv;
                    lv.x = __float2bfloat16(o0 - __bfloat162float(hv.x));
                    lv.y = __float2bfloat16(o1 - __bfloat162float(hv.y));
                    *(__nv_bfloat162*)&Cl[(size_t)r*N + c] = lv;
                }
            }
            if (r + 8 < M) {
                if (epi & EPI_RES) {
                    float2 rv = *(const float2*)&res[(size_t)(r+8)*N + c];
                    o2 += rv.x; o3 += rv.y;
                }
                if (epi & EPI_F32) {
                    float2 ov; ov.x = o2; ov.y = o3;
                    *(float2*)&C[(size_t)(r+8)*N + c] = ov;
                }
                if (epi & EPI_BF16) {
                    __nv_bfloat162 hv; hv.x = __float2bfloat16(o2); hv.y = __float2bfloat16(o3);
                    *(__nv_bfloat162*)&Ch[(size_t)(r+8)*N + c] = hv;
                    __nv_bfloat162 lv;
                    lv.x = __float2bfloat16(o2 - __bfloat162float(hv.x));
                    lv.y = __float2bfloat16(o3 - __bfloat162float(hv.y));
                    *(__nv_bfloat162*)&Cl[(size_t)(r+8)*N + c] = lv;
                }
            }
        }
    }
}

// ---------------- tensor-core flash attention ------------------------------------
__device__ __forceinline__ float lead_bias(int r, int c) {
    if (r == 0) return (c >= 1 && c < NUM_LEAD + 1) ? -99999.0f : 0.0f;
    if (r <= NUM_LEAD) {
        int st = NUM_LEAD + 1 + PATCHES * (r - 1);
        return (c >= st && c < st + PATCHES) ? 0.0f : -99999.0f;
    }
    return 0.0f;
}

#define FS 72   // smem row stride (bf16 elems); 144B -> conflict-free ldmatrix

__global__ __launch_bounds__(128)
void flash_mma(const __nv_bfloat16* __restrict__ qh, const __nv_bfloat16* __restrict__ ql,
               const __nv_bfloat16* __restrict__ kh, const __nv_bfloat16* __restrict__ kl,
               const __nv_bfloat16* __restrict__ vh,
               const float* __restrict__ amask,
               __nv_bfloat16* __restrict__ ch, __nv_bfloat16* __restrict__ cl)
{
    __shared__ __align__(16) __nv_bfloat16 sQh[64*FS], sQl[64*FS];
    __shared__ __align__(16) __nv_bfloat16 sKh[64*FS], sKl[64*FS];
    __shared__ __align__(16) __nv_bfloat16 sVh[64*FS];

    int tid = threadIdx.x, lane = tid & 31, w = tid >> 5;
    int q0 = blockIdx.x * 64;
    int h  = blockIdx.y, b = blockIdx.z;
    size_t base = (size_t)b * SEQ * HID + (size_t)h * DH;

    uint32_t uQh = (uint32_t)__cvta_generic_to_shared(sQh);
    uint32_t uQl = (uint32_t)__cvta_generic_to_shared(sQl);
    uint32_t uKh = (uint32_t)__cvta_generic_to_shared(sKh);
    uint32_t uKl = (uint32_t)__cvta_generic_to_shared(sKl);
    uint32_t uVh = (uint32_t)__cvta_generic_to_shared(sVh);

    // load Q (64x64, 2 planes): thread -> row tid>>1, 32-col half
    {
        int r = tid >> 1, c0 = (tid & 1) * 32;
        int gr = q0 + r; if (gr >= SEQ) gr = SEQ - 1;
        const uint4* sh = (const uint4*)(qh + base + (size_t)gr*HID + c0);
        const uint4* sl = (const uint4*)(ql + base + (size_t)gr*HID + c0);
        uint4* dh_ = (uint4*)(sQh + r*FS + c0);
        uint4* dl_ = (uint4*)(sQl + r*FS + c0);
        #pragma unroll
        for (int i = 0; i < 4; i++) { dh_[i] = sh[i]; dl_[i] = sl[i]; }
    }

    int arow_l = (lane & 7) + ((lane >> 3) & 1) * 8;
    int acol_l = (lane >> 4) * 8;
    int brow_l = (lane & 7) + ((lane >> 4) & 1) * 8;
    int bcol_l = ((lane >> 3) & 1) * 8;
    // trans (V) per-lane address parts
    int vmr = ((lane >> 3) & 1) * 8 + (lane & 7);   // row-in-ktile
    int vmc = (lane >> 4) * 8;                      // col offset (8-block)

    float o[8][4];
    #pragma unroll
    for (int j = 0; j < 8; j++)
        #pragma unroll
        for (int r = 0; r < 4; r++) o[j][r] = 0.0f;
    float m0 = -1e30f, m1 = -1e30f, l0 = 0.0f, l1 = 0.0f;

    int gr0 = q0 + w*16 + (lane >> 2);
    int gr1 = gr0 + 8;

    const int ntile = (SEQ + 63) / 64;   // 19
    for (int t = 0; t < ntile; t++) {
        int k0t = t * 64;
        __syncthreads();
        // load K (2 planes) + V (1 plane)
        {
            int r = tid >> 1, c0 = (tid & 1) * 32;
            int gsr = k0t + r; if (gsr >= SEQ) gsr = SEQ - 1;
            const uint4* skh = (const uint4*)(kh + base + (size_t)gsr*HID + c0);
            const uint4* skl = (const uint4*)(kl + base + (size_t)gsr*HID + c0);
            const uint4* svh = (const uint4*)(vh + base + (size_t)gsr*HID + c0);
            uint4* dkh = (uint4*)(sKh + r*FS + c0);
            uint4* dkl = (uint4*)(sKl + r*FS + c0);
            uint4* dvh = (uint4*)(sVh + r*FS + c0);
            #pragma unroll
            for (int i = 0; i < 4; i++) { dkh[i] = skh[i]; dkl[i] = skl[i]; dvh[i] = svh[i]; }
        }
        __syncthreads();

        // ---- S = Q K^T (bf16x3) ----
        float s[8][4];
        #pragma unroll
        for (int j = 0; j < 8; j++)
            #pragma unroll
            for (int r = 0; r < 4; r++) s[j][r] = 0.0f;

        #pragma unroll
        for (int kk = 0; kk < 4; kk++) {
            uint32_t aqh[4], aql[4];
            ldsm4(aqh, uQh + ((w*16 + arow_l)*FS + kk*16 + acol_l)*2);
            ldsm4(aql, uQl + ((w*16 + arow_l)*FS + kk*16 + acol_l)*2);
            #pragma unroll
            for (int jj = 0; jj < 4; jj++) {
                uint32_t bh[4], bl[4];
                ldsm4(bh, uKh + ((16*jj + brow_l)*FS + kk*16 + bcol_l)*2);
                ldsm4(bl, uKl + ((16*jj + brow_l)*FS + kk*16 + bcol_l)*2);
                mma16816(s[2*jj],   aqh, bh[0], bh[1]);
                mma16816(s[2*jj+1], aqh, bh[2], bh[3]);
                mma16816(s[2*jj],   aql, bh[0], bh[1]);
                mma16816(s[2*jj+1], aql, bh[2], bh[3]);
                mma16816(s[2*jj],   aqh, bl[0], bl[1]);
                mma16816(s[2*jj+1], aqh, bl[2], bl[3]);
            }
        }

        // ---- scale + masks ----
        bool lead = (q0 == 0 && w == 0);   // rows 0..15 only can be lead rows
        #pragma unroll
        for (int j = 0; j < 8; j++) {
            int c0 = k0t + j*8 + (lane & 3)*2;
            int c1 = c0 + 1;
            float am0 = (c0 < SEQ) ? amask[(size_t)b*SEQ + c0] : 0.0f;
            float am1 = (c1 < SEQ) ? amask[(size_t)b*SEQ + c1] : 0.0f;
            float v00 = s[j][0]*0.125f + am0;
            float v01 = s[j][1]*0.125f + am1;
            float v10 = s[j][2]*0.125f + am0;
            float v11 = s[j][3]*0.125f + am1;
            if (lead) {
                v00 += lead_bias(gr0, c0); v01 += lead_bias(gr0, c1);
                v10 += lead_bias(gr1, c0); v11 += lead_bias(gr1, c1);
            }
            if (c0 >= SEQ) { v00 = -1e30f; v10 = -1e30f; }
            if (c1 >= SEQ) { v01 = -1e30f; v11 = -1e30f; }
            s[j][0] = v00; s[j][1] = v01; s[j][2] = v10; s[j][3] = v11;
        }

        // ---- online softmax (rows gr0, gr1 per thread-group-of-4) ----
        float mt0 = -1e30f, mt1 = -1e30f;
        #pragma unroll
        for (int j = 0; j < 8; j++) {
            mt0 = fmaxf(mt0, fmaxf(s[j][0], s[j][1]));
            mt1 = fmaxf(mt1, fmaxf(s[j][2], s[j][3]));
        }
        mt0 = fmaxf(mt0, __shfl_xor_sync(0xffffffffu, mt0, 1));
        mt0 = fmaxf(mt0, __shfl_xor_sync(0xffffffffu, mt0, 2));
        mt1 = fmaxf(mt1, __shfl_xor_sync(0xffffffffu, mt1, 1));
        mt1 = fmaxf(mt1, __shfl_xor_sync(0xffffffffu, mt1, 2));
        float mn0 = fmaxf(m0, mt0), mn1 = fmaxf(m1, mt1);
        float corr0 = __expf(m0 - mn0), corr1 = __expf(m1 - mn1);
        m0 = mn0; m1 = mn1;
        float rs0 = 0.0f, rs1 = 0.0f;
        #pragma unroll
        for (int j = 0; j < 8; j++) {
            s[j][0] = __expf(s[j][0] - mn0);
            s[j][1] = __expf(s[j][1] - mn0);
            s[j][2] = __expf(s[j][2] - mn1);
            s[j][3] = __expf(s[j][3] - mn1);
            rs0 += s[j][0] + s[j][1];
            rs1 += s[j][2] + s[j][3];
        }
        rs0 += __shfl_xor_sync(0xffffffffu, rs0, 1);
        rs0 += __shfl_xor_sync(0xffffffffu, rs0, 2);
        rs1 += __shfl_xor_sync(0xffffffffu, rs1, 1);
        rs1 += __shfl_xor_sync(0xffffffffu, rs1, 2);
        l0 = l0 * corr0 + rs0;
        l1 = l1 * corr1 + rs1;
        #pragma unroll
        for (int j = 0; j < 8; j++) {
            o[j][0] *= corr0; o[j][1] *= corr0;
            o[j][2] *= corr1; o[j][3] *= corr1;
        }

        // ---- pack P into A fragments (hi + lo) ----
        uint32_t phA[8], phB[8], plA[8], plB[8];
        #pragma unroll
        for (int j = 0; j < 8; j++) {
            __nv_bfloat162 hA = __floats2bfloat162_rn(s[j][0], s[j][1]);
            __nv_bfloat162 hB = __floats2bfloat162_rn(s[j][2], s[j][3]);
            phA[j] = *(uint32_t*)&hA;
            phB[j] = *(uint32_t*)&hB;
            plA[j] = packbf2(s[j][0] - __bfloat162float(hA.x), s[j][1] - __bfloat162float(hA.y));
            plB[j] = packbf2(s[j][2] - __bfloat162float(hB.x), s[j][3] - __bfloat162float(hB.y));
        }

        // ---- O += P V  ((Ph+Pl)*Vh) ----
        #pragma unroll
        for (int kk = 0; kk < 4; kk++) {
            uint32_t aH[4] = { phA[2*kk], phB[2*kk], phA[2*kk+1], phB[2*kk+1] };
            uint32_t aL[4] = { plA[2*kk], plB[2*kk], plA[2*kk+1], plB[2*kk+1] };
            #pragma unroll
            for (int jj = 0; jj < 4; jj++) {
                uint32_t bv[4];
                ldsm4t(bv, uVh + ((kk*16 + vmr)*FS + jj*16 + vmc)*2);
                mma16816(o[2*jj],   aH, bv[0], bv[1]);
                mma16816(o[2*jj+1], aH, bv[2], bv[3]);
                mma16816(o[2*jj],   aL, bv[0], bv[1]);
                mma16816(o[2*jj+1], aL, bv[2], bv[3]);
            }
        }
    }

    // ---- normalize + store ctx hi/lo ----
    float inv0 = 1.0f / l0, inv1 = 1.0f / l1;
    #pragma unroll
    for (int j = 0; j < 8; j++) {
        int c = j*8 + (lane & 3)*2;
        if (gr0 < SEQ) {
            float a = o[j][0]*inv0, bb = o[j][1]*inv0;
            __nv_bfloat162 hv = __floats2bfloat162_rn(a, bb);
            size_t idx = base + (size_t)gr0*HID + c;
            *(__nv_bfloat162*)&ch[idx] = hv;
            __nv_bfloat162 lv = __floats2bfloat162_rn(a - __bfloat162float(hv.x),
                                                      bb - __bfloat162float(hv.y));
            *(__nv_bfloat162*)&cl[idx] = lv;
        }
        if (gr1 < SEQ) {
            float a = o[j][2]*inv1, bb = o[j][3]*inv1;
            __nv_bfloat162 hv = __floats2bfloat162_rn(a, bb);
            size_t idx = base + (size_t)gr1*HID + c;
            *(__nv_bfloat162*)&ch[idx] = hv;
            __nv_bfloat162 lv = __floats2bfloat162_rn(a - __bfloat162float(hv.x),
                                                      bb - __bfloat162float(hv.y));
            *(__nv_bfloat162*)&cl[idx] = lv;
        }
    }
}

// ---------------- LayerNorm (two-pass, optional bf16 split output) --------------
__global__ __launch_bounds__(256)
void ln_kernel(const float* __restrict__ x, const float* __restrict__ g,
               const float* __restrict__ bta, float* __restrict__ y,
               __nv_bfloat16* __restrict__ outh, __nv_bfloat16* __restrict__ outl)
{
    __shared__ float red[8];
    int row = blockIdx.x;
    int tid = threadIdx.x;
    const float* xr = x + (size_t)row * HID;

    float v[3];
    float s = 0.0f;
    #pragma unroll
    for (int i = 0; i < 3; i++) { v[i] = xr[tid + i*256]; s += v[i]; }

    #pragma unroll
    for (int off = 16; off >= 1; off >>= 1) s += __shfl_xor_sync(0xffffffffu, s, off);
    if ((tid & 31) == 0) red[tid >> 5] = s;
    __syncthreads();
    s = red[0]+red[1]+red[2]+red[3]+red[4]+red[5]+red[6]+red[7];
    float mean = s * (1.0f / HID);
    __syncthreads();

    float s2 = 0.0f;
    #pragma unroll
    for (int i = 0; i < 3; i++) { float d = v[i] - mean; s2 += d * d; }
    #pragma unroll
    for (int off = 16; off >= 1; off >>= 1) s2 += __shfl_xor_sync(0xffffffffu, s2, off);
    if ((tid & 31) == 0) red[tid >> 5] = s2;
    __syncthreads();
    s2 = red[0]+red[1]+red[2]+red[3]+red[4]+red[5]+red[6]+red[7];
    float rstd = rsqrtf(s2 * (1.0f / HID) + 1e-12f);

    #pragma unroll
    for (int i = 0; i < 3; i++) {
        int c = tid + i*256;
        float val = g[c] * (v[i] - mean) * rstd + bta[c];
        y[(size_t)row*HID + c] = val;
        if (outh) {
            __nv_bfloat16 hv = __float2bfloat16(val);
            outh[(size_t)row*HID + c] = hv;
            outl[(size_t)row*HID + c] = __float2bfloat16(val - __bfloat162float(hv));
        }
    }
}

// ---------------- launch --------------------------------------------------------
extern "C" void kernel_launch(void* const* d_in, const int* in_sizes, int n_in,
                              void* d_out, int out_size)
{
    const float* X     = (const float*)d_in[0];
    const float* amask = (const float*)d_in[1];
    const float* Wq = (const float*)d_in[2];  const float* bq = (const float*)d_in[3];
    const float* Wk = (const float*)d_in[4];  const float* bk = (const float*)d_in[5];
    const float* Wv = (const float*)d_in[6];  const float* bv = (const float*)d_in[7];
    const float* Wo = (const float*)d_in[8];  const float* bo = (const float*)d_in[9];
    const float* g1 = (const float*)d_in[10]; const float* b1 = (const float*)d_in[11];
    const float* Wi = (const float*)d_in[12]; const float* bi = (const float*)d_in[13];
    const float* Wd = (const float*)d_in[14]; const float* bd = (const float*)d_in[15];
    const float* g2 = (const float*)d_in[16]; const float* b2 = (const float*)d_in[17];

    float *t1, *attn;
    cudaGetSymbolAddress((void**)&t1,   g_t1);
    cudaGetSymbolAddress((void**)&attn, g_attn);

    __nv_bfloat16 *ah, *al, *bh, *bl, *qh_, *ql_, *kh_, *kl_, *vh_, *vl_;
    cudaGetSymbolAddress((void**)&ah,  g_ah);  cudaGetSymbolAddress((void**)&al,  g_al);
    cudaGetSymbolAddress((void**)&bh,  g_bh);  cudaGetSymbolAddress((void**)&bl,  g_bl);
    cudaGetSymbolAddress((void**)&qh_, g_qh);  cudaGetSymbolAddress((void**)&ql_, g_ql);
    cudaGetSymbolAddress((void**)&kh_, g_kh);  cudaGetSymbolAddress((void**)&kl_, g_kl);
    cudaGetSymbolAddress((void**)&vh_, g_vh);  cudaGetSymbolAddress((void**)&vl_, g_vl);

    __nv_bfloat16 *wqh, *wql, *wkh, *wkl, *wvh, *wvl, *woh, *wol, *wih, *wil, *wdh, *wdl;
    cudaGetSymbolAddress((void**)&wqh, g_wqh); cudaGetSymbolAddress((void**)&wql, g_wql);
    cudaGetSymbolAddress((void**)&wkh, g_wkh); cudaGetSymbolAddress((void**)&wkl, g_wkl);
    cudaGetSymbolAddress((void**)&wvh, g_wvh); cudaGetSymbolAddress((void**)&wvl, g_wvl);
    cudaGetSymbolAddress((void**)&woh, g_woh); cudaGetSymbolAddress((void**)&wol, g_wol);
    cudaGetSymbolAddress((void**)&wih, g_wih); cudaGetSymbolAddress((void**)&wil, g_wil);
    cudaGetSymbolAddress((void**)&wdh, g_wdh); cudaGetSymbolAddress((void**)&wdl, g_wdl);

    dim3 blk(256);
    const int MB = (MROWS + 127) / 128;      // 76
    dim3 gGH(HID/128, MB);
    dim3 gGI(INTER/128, MB);

    // 0: all weight transpose-splits in one launch
    tsplit_all<<<6912, blk>>>(Wq, Wk, Wv, Wo, Wi, Wd,
                              wqh, wql, wkh, wkl, wvh, wvl, woh, wol,
                              wih, wil, wdh, wdl);
    // 1: split X
    int nX4 = (MROWS*HID)/4;
    split_kernel<<<(nX4 + 255)/256, blk>>>(X, ah, al, nX4);

    // 2-4: QKV (bf16 split outputs only)
    mma_gemm<<<gGH, blk>>>(ah, al, wqh, wql, bq, nullptr, nullptr, qh_, ql_, MROWS, HID, HID, EPI_BF16);
    mma_gemm<<<gGH, blk>>>(ah, al, wkh, wkl, bk, nullptr, nullptr, kh_, kl_, MROWS, HID, HID, EPI_BF16);
    mma_gemm<<<gGH, blk>>>(ah, al, wvh, wvl, bv, nullptr, nullptr, vh_, vl_, MROWS, HID, HID, EPI_BF16);

    // 5: flash attention (tensor cores) -> ctx split into ah/al
    dim3 gF((SEQ + 63)/64, NH, BATCH);
    flash_mma<<<gF, 128>>>(qh_, ql_, kh_, kl_, vh_, amask, ah, al);

    // 6: O-proj + residual -> t1 fp32
    mma_gemm<<<gGH, blk>>>(ah, al, woh, wol, bo, X, t1, nullptr, nullptr, MROWS, HID, HID, EPI_RES|EPI_F32);
    // 7: LN1 -> attn fp32 + split into ah/al
    ln_kernel<<<MROWS, blk>>>(t1, g1, b1, attn, ah, al);

    // 8: FFN1 + gelu -> inter split into bh/bl
    mma_gemm<<<gGI, blk>>>(ah, al, wih, wil, bi, nullptr, nullptr, bh, bl, MROWS, INTER, HID, EPI_GELU|EPI_BF16);
    // 9: FFN2 + residual -> t1 fp32
    mma_gemm<<<gGH, blk>>>(bh, bl, wdh, wdl, bd, attn, t1, nullptr, nullptr, MROWS, HID, INTER, EPI_RES|EPI_F32);
    // 10: LN2 -> output
    ln_kernel<<<MROWS, blk>>>(t1, g2, b2, (float*)d_out, nullptr, nullptr);
}